// round 15
// baseline (speedup 1.0000x reference)
#include <cuda_runtime.h>
#include <cstdint>

// Problem constants
#define BATCH 4
#define CH    64
#define HH    64
#define WW    64
#define QHH   128
#define QWW   128
#define HID   256
#define OUT3  1728      // C*9*3
#define NK    576       // C*9
#define EPSV  1e-6f

// pw table, transposed: row k (576) x 12 floats [s0o0 s0o1 s0o2 s1o0 ... s3o2]
__device__ float g_pwT[NK * 12];

// ---------------------------------------------------------------------------
// Kernel A: MLP for the 4 parity classes -> g_pwT. Atomic-free, init-free.
// ---------------------------------------------------------------------------
__global__ void __launch_bounds__(256) mlp_pw_kernel(
    const float* __restrict__ coord, const float* __restrict__ cell,
    const float* __restrict__ w1,    const float* __restrict__ b1,
    const float* __restrict__ w2,    const float* __restrict__ b2)
{
    __shared__ float s_h[4][HID];        // hdd for the 4 parity classes
    __shared__ float s_part[16][16][4];  // [jsub][col][s]

    int tid = threadIdx.x;

    {
        int j = tid;
        #pragma unroll
        for (int s = 0; s < 4; ++s) {
            int py = s >> 1, px = s & 1;
            int qs = py * QWW + px;           // representative query (batch 0)
            float cy = coord[qs * 2 + 0];
            float cx = coord[qs * 2 + 1];
            float ly = cell[qs * 2 + 0];
            float lx = cell[qs * 2 + 1];
            float cy_ = cy - ly * 0.5f;
            float cx_ = cx - lx * 0.5f;
            float cqy = fminf(fmaxf(cy_ + EPSV, -1.0f + EPSV), 1.0f - EPSV);
            float cqx = fminf(fmaxf(cx_ + EPSV, -1.0f + EPSV), 1.0f - EPSV);
            float fy = ((cqy + 1.0f) * 64.0f - 1.0f) * 0.5f;
            float fx = ((cqx + 1.0f) * 64.0f - 1.0f) * 0.5f;
            float iy = fminf(fmaxf(rintf(fy), 0.0f), 63.0f);
            float ix = fminf(fmaxf(rintf(fx), 0.0f), 63.0f);
            float qcy = -1.0f + 2.0f * iy / 64.0f;
            float qcx = -1.0f + 2.0f * ix / 64.0f;
            float ry = (cy_ - qcy) * 32.0f;
            float rx = (cx_ - qcx) * 32.0f;
            float rr = ly * 32.0f;
            float h = ry * w1[j] + rx * w1[HID + j] + rr * w1[2 * HID + j] + b1[j];
            s_h[s][j] = fmaxf(h, 0.0f);
        }
    }
    __syncthreads();

    int col  = tid & 15;                        // 0..15
    int jsub = tid >> 4;                        // 0..15
    int k3   = blockIdx.x * 16 + col;           // 0..1727
    int j0   = jsub * 16;

    float a0 = 0.f, a1 = 0.f, a2 = 0.f, a3 = 0.f;
    const float* wp = w2 + (size_t)j0 * OUT3 + k3;
    #pragma unroll
    for (int j = 0; j < 16; ++j) {
        float w = wp[(size_t)j * OUT3];
        int jj = j0 + j;
        a0 = fmaf(s_h[0][jj], w, a0);
        a1 = fmaf(s_h[1][jj], w, a1);
        a2 = fmaf(s_h[2][jj], w, a2);
        a3 = fmaf(s_h[3][jj], w, a3);
    }
    s_part[jsub][col][0] = a0;
    s_part[jsub][col][1] = a1;
    s_part[jsub][col][2] = a2;
    s_part[jsub][col][3] = a3;
    __syncthreads();

    if (tid < 64) {
        int oc = tid >> 2;          // 0..15
        int os = tid & 3;           // 0..3
        int k3o = blockIdx.x * 16 + oc;
        float v = b2[k3o];
        #pragma unroll
        for (int t = 0; t < 16; ++t) v += s_part[t][oc][os];
        int k = k3o / 3;
        int o = k3o - k * 3;
        g_pwT[k * 12 + os * 3 + o] = v;
    }
}

// ---------------------------------------------------------------------------
// f32x2 packed helpers (FFMA2 — PTX-only on sm_10x)
// ---------------------------------------------------------------------------
__device__ __forceinline__ void ffma2(unsigned long long& d,
                                      unsigned long long a,
                                      unsigned long long b)
{
    asm("fma.rn.f32x2 %0, %1, %2, %0;" : "+l"(d) : "l"(a), "l"(b));
}
__device__ __forceinline__ void addf2(unsigned long long& d, unsigned long long a)
{
    asm("add.rn.f32x2 %0, %0, %1;" : "+l"(d) : "l"(a));
}
__device__ __forceinline__ unsigned long long pack2(float f)
{
    unsigned long long r;
    asm("mov.b64 %0, {%1, %1};" : "=l"(r) : "f"(f));
    return r;
}

// ---------------------------------------------------------------------------
// Kernel B: 4 px/lane, dx-column restructure + double-buffered prefetch of
// pw (next tap) and R-column (next group), PDL overlap with kernel A.
// grid = 128 (1 block/SM), block = 512 (16 warps), k split 16 warps x 4 ch.
// Groups g = (cc,dx): only one 6-row R column live (12 regs) -> prefetch
// registers fit under the 128-reg/thread budget with zero spills.
// ---------------------------------------------------------------------------
#define TW3   34
#define NROWS 6
#define CHS   (NROWS * TW3)             // 204 floats per channel
#define TILE_WORDS (CH * CHS)           // 13056
#define PW_WORDS   (NK * 12)            // 6912
// reduction view: [16 warps][24 accs][33] ull = 101376 B (> tile+pw = 79872)
#define SMEM_B (16 * 24 * 33 * 8)

__global__ void __launch_bounds__(512, 1) metasr_main_kernel(
    const float* __restrict__ feat, float* __restrict__ out)
{
    extern __shared__ float smem[];
    float* s_tile = smem;                  // [64][6][34]
    float* s_pw   = smem + TILE_WORDS;     // [576][12]

    int tid = threadIdx.x;
    int bx  = blockIdx.x;                  // 0..127
    int b   = bx >> 5;
    int y0  = ((bx >> 1) & 15) * 4;        // first of 4 LR rows
    int x0  = (bx & 1) * 32;               // column half

    const float* fb = feat + (size_t)b * CH * HH * WW;

    // ---- feat tile first (independent of kernel A -> overlaps it via PDL) --
    // halo columns: tile col 0 (gx = x0-1) and col 33 (gx = x0+32)
    for (int i = tid; i < CH * NROWS * 2; i += 512) {   // 768
        int c    = i / 12;
        int rem  = i - c * 12;
        int rr   = rem >> 1;
        int side = rem & 1;
        int gy   = y0 - 1 + rr;
        int gx   = x0 - 1 + side * 33;
        float v = 0.0f;
        if ((unsigned)gy < 64u && (unsigned)gx < 64u)
            v = fb[((c << 6) + gy) * 64 + gx];
        s_tile[c * CHS + rr * TW3 + side * 33] = v;
    }

    // interior: 32 cols per row via float4 loads
    #pragma unroll
    for (int it = 0; it < 6; ++it) {                    // 3072 total
        int i   = it * 512 + tid;
        int c   = i / 48;
        int rem = i - c * 48;
        int rr  = rem >> 3;
        int q   = rem & 7;
        int gy  = y0 - 1 + rr;
        float4 v = make_float4(0.f, 0.f, 0.f, 0.f);
        if ((unsigned)gy < 64u)
            v = *(const float4*)(fb + ((c << 6) + gy) * 64 + x0 + q * 4);
        float* dst = s_tile + c * CHS + rr * TW3 + 1 + q * 4;
        dst[0] = v.x; dst[1] = v.y; dst[2] = v.z; dst[3] = v.w;
    }

    // ---- wait for kernel A's g_pwT, then load it ----
    cudaGridDependencySynchronize();
    {
        const float4* src = (const float4*)g_pwT;
        float4* dst = (float4*)s_pw;
        for (int i = tid; i < PW_WORDS / 4; i += 512) dst[i] = src[i];
    }
    __syncthreads();

    // ---- main loop: warp w owns channels [4w, 4w+4) ----
    int w    = tid >> 5;
    int lane = tid & 31;

    const float* tw4 = s_tile + (w << 2) * CHS + lane;
    const ulonglong2* pk0 = (const ulonglong2*)s_pw + (w * 36) * 3;  // 36 k-rows

    unsigned long long acc[24];
    #pragma unroll
    for (int i = 0; i < 24; ++i) acc[i] = 0ull;

    // double-buffered R column (6 rows) and pw tap (3 ull2)
    unsigned long long R[2][6];
    ulonglong2 P[2][3];

    // init: R column for group 0 (cc=0,dx=0); pw for step 0 (cc=0,dy=0,dx=0)
    #pragma unroll
    for (int rr = 0; rr < 6; ++rr) R[0][rr] = pack2(tw4[rr * TW3]);
    P[0][0] = pk0[0]; P[0][1] = pk0[1]; P[0][2] = pk0[2];

    #pragma unroll
    for (int g = 0; g < 12; ++g) {            // group = (cc, dx)
        const int cc = g / 3, dx = g % 3;
        const int cb = g & 1, nb = cb ^ 1;

        // prefetch next group's R column
        if (g < 11) {
            const int gn = g + 1, ccn = gn / 3, dxn = gn % 3;
            #pragma unroll
            for (int rr = 0; rr < 6; ++rr)
                R[nb][rr] = pack2(tw4[ccn * CHS + rr * TW3 + dxn]);
        }

        #pragma unroll
        for (int dy = 0; dy < 3; ++dy) {
            const int s  = g * 3 + dy;        // global step 0..35
            const int pb = s & 1, pn = pb ^ 1;

            // prefetch next tap's pw
            if (s < 35) {
                const int sn  = s + 1;
                const int gg  = sn / 3, ddy = sn % 3;
                const int tcc = gg / 3, tdx = gg % 3;
                const ulonglong2* p = pk0 + tcc * 27 + (ddy * 3 + tdx) * 3;
                P[pn][0] = p[0]; P[pn][1] = p[1]; P[pn][2] = p[2];
            }

            const ulonglong2 p01 = P[pb][0];
            const ulonglong2 p23 = P[pb][1];
            const ulonglong2 p45 = P[pb][2];
            #pragma unroll
            for (int r = 0; r < 4; ++r) {
                const unsigned long long F = R[cb][dy + r];
                ffma2(acc[r * 6 + 0], F, p01.x);
                ffma2(acc[r * 6 + 1], F, p01.y);
                ffma2(acc[r * 6 + 2], F, p23.x);
                ffma2(acc[r * 6 + 3], F, p23.y);
                ffma2(acc[r * 6 + 4], F, p45.x);
                ffma2(acc[r * 6 + 5], F, p45.y);
            }
        }
    }

    // ---- cross-warp reduction: s_red[w(16)][a(24)][33] padded ull ----
    __syncthreads();
    unsigned long long* s_red = (unsigned long long*)smem;
    #pragma unroll
    for (int a = 0; a < 24; ++a)
        s_red[(w * 24 + a) * 33 + lane] = acc[a];
    __syncthreads();

    // pass 2: 768 output ull = (r 4) x (col 32) x (a 6); 2x8-way reduce
    #pragma unroll
    for (int ii = 0; ii < 2; ++ii) {
        int i = ii * 512 + tid;
        if (i < 768) {
            int r   = i / 192;
            int rem = i - r * 192;
            int col = rem / 6;
            int a   = rem - col * 6;

            int srcidx = r * 6 + a;
            unsigned long long v0 = s_red[srcidx * 33 + col];
            unsigned long long v1 = s_red[(8 * 24 + srcidx) * 33 + col];
            #pragma unroll
            for (int ww = 1; ww < 8; ++ww) {
                addf2(v0, s_red[(ww * 24 + srcidx) * 33 + col]);
                addf2(v1, s_red[((ww + 8) * 24 + srcidx) * 33 + col]);
            }
            addf2(v0, v1);

            int yq = 2 * (y0 + r) + (a / 3);   // a 0-2 -> HR row 2y, 3-5 -> 2y+1
            int xq = 2 * (x0 + col);
            int jj = a % 3;
            size_t base = ((size_t)(b * QHH + yq) * QWW + xq) * 3 + jj * 2;
            *(unsigned long long*)(out + base) = v0;
        }
    }
}

// ---------------------------------------------------------------------------
extern "C" void kernel_launch(void* const* d_in, const int* in_sizes, int n_in,
                              void* d_out, int out_size)
{
    const float* feat  = (const float*)d_in[0];
    const float* coord = (const float*)d_in[1];
    const float* cell  = (const float*)d_in[2];
    const float* w1    = (const float*)d_in[3];
    const float* b1    = (const float*)d_in[4];
    const float* w2    = (const float*)d_in[5];
    const float* b2    = (const float*)d_in[6];
    float* out = (float*)d_out;

    cudaFuncSetAttribute(metasr_main_kernel,
                         cudaFuncAttributeMaxDynamicSharedMemorySize, SMEM_B);

    mlp_pw_kernel<<<108, 256>>>(coord, cell, w1, b1, w2, b2);

    // Main kernel with Programmatic Dependent Launch: starts while kernel A
    // runs, loads its feat tile, then grid-dep-syncs before reading g_pwT.
    cudaLaunchConfig_t cfg = {};
    cfg.gridDim  = dim3(128, 1, 1);
    cfg.blockDim = dim3(512, 1, 1);
    cfg.dynamicSmemBytes = SMEM_B;
    cfg.stream = 0;
    cudaLaunchAttribute attrs[1];
    attrs[0].id = cudaLaunchAttributeProgrammaticStreamSerialization;
    attrs[0].val.programmaticStreamSerializationAllowed = 1;
    cfg.attrs = attrs;
    cfg.numAttrs = 1;
    cudaLaunchKernelEx(&cfg, metasr_main_kernel, feat, out);
}